// round 6
// baseline (speedup 1.0000x reference)
#include <cuda_runtime.h>

#define BB 32
#define SS 1024
#define DD 512
#define DD4 (DD/4)
#define MAXL 8192   // durations in [1,8], S=1024 -> mel_len <= 8192
#define CH 8        // idx-build chunks per batch (32*8 = 256 blocks)

// Scratch (no device allocation allowed)
// g_idx[r] = global source row b*S+i, or -1 for padding
__device__ __align__(16) int g_idx[BB * MAXL];

// ---------------------------------------------------------------------------
// K1: fused scan + index build, parallel over 32*CH blocks.
// ---------------------------------------------------------------------------
__global__ __launch_bounds__(SS)
void lr_scan_idx_kernel(const int* __restrict__ dur,
                        float* __restrict__ mel_len_out,
                        float* __restrict__ mask_out,
                        int max_len, int rows_pc, int has_tail)
{
    __shared__ int s[SS];
    __shared__ int warp_sums[32];

    const int b     = blockIdx.x >> 3;        // / CH
    const int chunk = blockIdx.x & (CH - 1);  // % CH
    const int tid   = threadIdx.x;
    const int lane  = tid & 31;
    const int wid   = tid >> 5;

    int v = dur[b * SS + tid];
    #pragma unroll
    for (int off = 1; off < 32; off <<= 1) {
        int n = __shfl_up_sync(0xffffffff, v, off);
        if (lane >= off) v += n;
    }
    if (lane == 31) warp_sums[wid] = v;
    __syncthreads();
    if (wid == 0) {
        int w = warp_sums[lane];
        #pragma unroll
        for (int off = 1; off < 32; off <<= 1) {
            int n = __shfl_up_sync(0xffffffff, w, off);
            if (lane >= off) w += n;
        }
        warp_sums[lane] = w;
    }
    __syncthreads();
    s[tid] = v + ((wid > 0) ? warp_sums[wid - 1] : 0);
    __syncthreads();

    const int mel = s[SS - 1];
    if (has_tail && chunk == 0 && tid == 0) mel_len_out[b] = (float)mel;

    const int t0 = chunk * rows_pc;
    const int t1 = min(t0 + rows_pc, max_len);
    for (int t = t0 + tid; t < t1; t += SS) {
        const int r = b * max_len + t;
        if (t >= mel) {
            g_idx[r] = -1;
            if (has_tail) mask_out[r] = 1.0f;
        } else {
            int lo = 0, hi = SS - 1;   // first i with s[i] > t
            #pragma unroll
            for (int it = 0; it < 10; ++it) {
                if (lo < hi) {
                    int mid = (lo + hi) >> 1;
                    if (s[mid] > t) hi = mid; else lo = mid + 1;
                }
            }
            g_idx[r] = b * SS + lo;
            if (has_tail) mask_out[r] = 0.0f;
        }
    }
}

// ---------------------------------------------------------------------------
// K2: expand with L2-traffic reuse. ONE WARP PER FOUR CONSECUTIVE ROWS.
//  - one int4 broadcast load gets all 4 source indices
//  - row loaded from x only when its src differs from previous row (runs
//    average ~4.5, so ~1.9 unique loads per group) -> L2 read traffic / ~2.4
//  - straight-line, warp-uniform branches, no loop-carried dependence
//  - __stcs streaming stores
// ---------------------------------------------------------------------------
__global__ __launch_bounds__(256)
void lr_expand_kernel(const float4* __restrict__ x4,
                      float4* __restrict__ out4,
                      int ngroups)
{
    const int g    = (blockIdx.x * blockDim.x + threadIdx.x) >> 5;
    const int lane = threadIdx.x & 31;
    if (g >= ngroups) return;

    const int4 ss = __ldg(&((const int4*)g_idx)[g]);
    const int s0 = ss.x, s1 = ss.y, s2 = ss.z, s3 = ss.w;

    const float4 z = make_float4(0.f, 0.f, 0.f, 0.f);
    float4 a0=z,a1=z,a2=z,a3=z;
    float4 b0=z,b1=z,b2=z,b3=z;
    float4 c0=z,c1=z,c2=z,c3=z;
    float4 d0=z,d1=z,d2=z,d3=z;

    // issue all distinct loads first (independent -> high MLP)
    if (s0 >= 0) {
        const long ib = (long)s0 * DD4 + lane;
        a0 = __ldg(&x4[ib]);      a1 = __ldg(&x4[ib + 32]);
        a2 = __ldg(&x4[ib + 64]); a3 = __ldg(&x4[ib + 96]);
    }
    if (s1 != s0 && s1 >= 0) {
        const long ib = (long)s1 * DD4 + lane;
        b0 = __ldg(&x4[ib]);      b1 = __ldg(&x4[ib + 32]);
        b2 = __ldg(&x4[ib + 64]); b3 = __ldg(&x4[ib + 96]);
    }
    if (s2 != s1 && s2 >= 0) {
        const long ib = (long)s2 * DD4 + lane;
        c0 = __ldg(&x4[ib]);      c1 = __ldg(&x4[ib + 32]);
        c2 = __ldg(&x4[ib + 64]); c3 = __ldg(&x4[ib + 96]);
    }
    if (s3 != s2 && s3 >= 0) {
        const long ib = (long)s3 * DD4 + lane;
        d0 = __ldg(&x4[ib]);      d1 = __ldg(&x4[ib + 32]);
        d2 = __ldg(&x4[ib + 64]); d3 = __ldg(&x4[ib + 96]);
    }

    // resolve run copies (register MOVs)
    if (s1 == s0) { b0=a0; b1=a1; b2=a2; b3=a3; }
    if (s2 == s1) { c0=b0; c1=b1; c2=b2; c3=b3; }
    if (s3 == s2) { d0=c0; d1=c1; d2=c2; d3=c3; }

    const long ob = (long)g * (4 * DD4) + lane;
    __stcs(&out4[ob],             a0);
    __stcs(&out4[ob +        32], a1);
    __stcs(&out4[ob +        64], a2);
    __stcs(&out4[ob +        96], a3);
    __stcs(&out4[ob + DD4],       b0);
    __stcs(&out4[ob + DD4 +  32], b1);
    __stcs(&out4[ob + DD4 +  64], b2);
    __stcs(&out4[ob + DD4 +  96], b3);
    __stcs(&out4[ob + 2*DD4],     c0);
    __stcs(&out4[ob + 2*DD4+ 32], c1);
    __stcs(&out4[ob + 2*DD4+ 64], c2);
    __stcs(&out4[ob + 2*DD4+ 96], c3);
    __stcs(&out4[ob + 3*DD4],     d0);
    __stcs(&out4[ob + 3*DD4+ 32], d1);
    __stcs(&out4[ob + 3*DD4+ 64], d2);
    __stcs(&out4[ob + 3*DD4+ 96], d3);
}

// ---------------------------------------------------------------------------
extern "C" void kernel_launch(void* const* d_in, const int* in_sizes, int n_in,
                              void* d_out, int out_size)
{
    const float* x   = (const float*)d_in[0];
    const int*   dur = (const int*)d_in[1];
    float*       out = (float*)d_out;

    // Recover max_len from out_size (tuple layout vs expanded-only).
    long L;
    int has_tail;
    long os = (long)out_size;
    if ((os - BB) > 0 && ((os - BB) % ((long)BB * (DD + 1))) == 0) {
        L = (os - BB) / ((long)BB * (DD + 1));
        has_tail = 1;
    } else {
        L = os / ((long)BB * DD);
        has_tail = 0;
    }
    if (L <= 0 || L > MAXL) return;

    const int max_len = (int)L;
    const int rows_pc = (max_len + CH - 1) / CH;

    float* mel_len_out = out + (long)BB * max_len * DD;   // B floats
    float* mask_out    = mel_len_out + BB;                // B*L floats

    lr_scan_idx_kernel<<<BB * CH, SS>>>(dur, mel_len_out, mask_out,
                                        max_len, rows_pc, has_tail);

    {
        const int total_rows = BB * max_len;     // multiple of 32
        const int ngroups = total_rows >> 2;     // 4 rows per warp
        const int warps_per_block = 256 / 32;
        const int blocks = (ngroups + warps_per_block - 1) / warps_per_block;
        lr_expand_kernel<<<blocks, 256>>>((const float4*)x, (float4*)out, ngroups);
    }
}